// round 3
// baseline (speedup 1.0000x reference)
#include <cuda_runtime.h>
#include <cstdint>
#include <cstddef>

// SubnetGate: hard one-hot MoE MLP.
//   out[t] = relu(x[t] @ W1[e] + b1[e]) @ W2[e] + b2[e],  e = groups[t]
// B=8192, D_IN=512, D_H=2048, D_OUT=512, E=8, fp32 activations/weights.
// groups arrives as int32 (harness normalizes int64) — router probes layout.

namespace {
constexpr int B_TOK  = 8192;
constexpr int D_INc  = 512;
constexpr int D_Hc   = 2048;
constexpr int D_OUTc = 512;
constexpr int NE     = 8;
constexpr int TM     = 128;   // M tile
constexpr int NT_MAX = 72;    // max padded M tiles: sum ceil(c_e/128) <= 64+7
constexpr int BK     = 32;
constexpr int BN     = 128;
constexpr int AS_STRIDE = 36;   // banks (4m+k)%32 distinct
constexpr int BS_STRIDE = 136;  // 136%32==8 -> banks (8k+n)%32 distinct
}

__device__ int   g_perm[NT_MAX * TM];       // padded sorted pos -> token id (-1 = pad)
__device__ int   g_tile_expert[NT_MAX];     // tile -> expert (-1 = inactive)
__device__ float g_h[(size_t)NT_MAX * TM * D_Hc];  // hidden acts, sorted layout

__device__ __forceinline__ float f2tf32(float x) {
    uint32_t r;
    asm("cvt.rna.tf32.f32 %0, %1;" : "=r"(r) : "f"(x));
    return __uint_as_float(r);
}

// ---------------------------------------------------------------------------
// Router. Single block. Probes whether groups is int32 or int64 on device:
// int64 data (values 0..7, LE) has all odd int32 words == 0 across the first
// B words; int32 data has ~7/8 of odd words nonzero. Then counting-sort into
// 128-row padded per-expert tiles.
// ---------------------------------------------------------------------------
__global__ void route_kernel(const int* __restrict__ g32) {
    __shared__ int cnt[NE];
    __shared__ int base[NE + 1];
    __shared__ int cur[NE];
    __shared__ int odd_or;
    const int tid = threadIdx.x;

    if (tid < NE) cnt[tid] = 0;
    if (tid == 0) odd_or = 0;
    __syncthreads();

    // Dtype probe: OR all odd-index words among the first B_TOK int32s.
    int acc_or = 0;
    for (int i = 2 * tid + 1; i < B_TOK; i += 2 * blockDim.x) acc_or |= g32[i];
    if (acc_or) atomicOr(&odd_or, 1);
    __syncthreads();
    const bool is_i32 = (odd_or != 0);

    for (int t = tid; t < B_TOK; t += blockDim.x) {
        int e = is_i32 ? g32[t] : g32[2 * t];
        atomicAdd(&cnt[e & (NE - 1)], 1);
    }
    __syncthreads();

    if (tid == 0) {
        int b = 0;
        for (int e = 0; e < NE; e++) {
            base[e] = b;
            cur[e]  = b;
            b += ((cnt[e] + TM - 1) / TM) * TM;
        }
        base[NE] = b;
    }
    __syncthreads();

    for (int i = tid; i < NT_MAX * TM; i += blockDim.x) g_perm[i] = -1;
    for (int t = tid; t < NT_MAX; t += blockDim.x) {
        int row0 = t * TM;
        int e = -1;
        if (row0 < base[NE]) {
            for (int k = 0; k < NE; k++)
                if (row0 >= base[k] && row0 < base[k + 1]) e = k;
        }
        g_tile_expert[t] = e;
    }
    __syncthreads();

    for (int t = tid; t < B_TOK; t += blockDim.x) {
        int e = (is_i32 ? g32[t] : g32[2 * t]) & (NE - 1);
        int pos = atomicAdd(&cur[e], 1);
        g_perm[pos] = t;
    }
}

// ---------------------------------------------------------------------------
// Grouped GEMM: C = op(A_rows @ W[e] + bias[e])
//   GATHER:  A rows gathered via g_perm (layer 1, A = x);  else A = g_h (sorted)
//   RELU:    apply relu (layer 1)
//   SCATTER: write rows to out via g_perm (layer 2);       else write g_h
// 128x128 block tile, BK=32, 8 warps (2x4), 64x32 warp tile, tf32 m16n8k8.
// ---------------------------------------------------------------------------
template <int K, int N, bool GATHER, bool RELU, bool SCATTER>
__global__ __launch_bounds__(256)
void gemm_kernel(const float* __restrict__ Ain,
                 const float* __restrict__ W,
                 const float* __restrict__ bias,
                 float* __restrict__ Oin) {
    __shared__ float As[TM * AS_STRIDE];
    __shared__ float Bs[BK * BS_STRIDE];

    const int tile = blockIdx.x;
    const int e = g_tile_expert[tile];
    if (e < 0) return;

    const float* A   = GATHER  ? Ain : g_h;
    float*       out = SCATTER ? Oin : g_h;

    const int n0 = blockIdx.y * BN;
    const float* Wp = W + (size_t)e * K * N + n0;
    const float* bp = bias + (size_t)e * N + n0;

    const int tid  = threadIdx.x;
    const int lane = tid & 31;
    const int warp = tid >> 5;
    const int wm   = warp >> 2;  // 0..1
    const int wn   = warp & 3;   // 0..3

    // Per-thread A-row pointers: thread loads float4 column (tid&7), rows (tid>>3)+32j.
    const float* arow[4];
#pragma unroll
    for (int j = 0; j < 4; j++) {
        int r = (tid >> 3) + 32 * j;
        if (GATHER) {
            int tok = g_perm[tile * TM + r];
            arow[j] = (tok >= 0) ? (A + (size_t)tok * K) : nullptr;
        } else {
            arow[j] = A + ((size_t)tile * TM + r) * K;
        }
    }

    float acc[4][4][4];
#pragma unroll
    for (int i = 0; i < 4; i++)
#pragma unroll
        for (int j = 0; j < 4; j++)
#pragma unroll
            for (int q = 0; q < 4; q++) acc[i][j][q] = 0.f;

    const int ac4 = (tid & 7) * 4;
    const int bc4 = (tid & 31) * 4;

    for (int k0 = 0; k0 < K; k0 += BK) {
        // Stage A (128x32) — gathered rows, tf32-rounded at store.
#pragma unroll
        for (int j = 0; j < 4; j++) {
            int r = (tid >> 3) + 32 * j;
            float4 v = make_float4(0.f, 0.f, 0.f, 0.f);
            if (arow[j]) v = *(const float4*)(arow[j] + k0 + ac4);
            float* dst = &As[r * AS_STRIDE + ac4];
            dst[0] = f2tf32(v.x); dst[1] = f2tf32(v.y);
            dst[2] = f2tf32(v.z); dst[3] = f2tf32(v.w);
        }
        // Stage B (32x128) — W[e][k0+kk][n0..n0+127].
#pragma unroll
        for (int j = 0; j < 4; j++) {
            int kk = (tid >> 5) + 8 * j;
            float4 v = *(const float4*)(Wp + (size_t)(k0 + kk) * N + bc4);
            float* dst = &Bs[kk * BS_STRIDE + bc4];
            dst[0] = f2tf32(v.x); dst[1] = f2tf32(v.y);
            dst[2] = f2tf32(v.z); dst[3] = f2tf32(v.w);
        }
        __syncthreads();

#pragma unroll
        for (int kk = 0; kk < BK; kk += 8) {
            uint32_t af[4][4], bf[4][2];
            const int kq = kk + (lane & 3);
#pragma unroll
            for (int mf = 0; mf < 4; mf++) {
                int m = wm * 64 + mf * 16 + (lane >> 2);
                // PTX m16n8k8.tf32 A fragment:
                //   a0=(m,k), a1=(m+8,k), a2=(m,k+4), a3=(m+8,k+4)
                af[mf][0] = __float_as_uint(As[m * AS_STRIDE + kq]);
                af[mf][1] = __float_as_uint(As[(m + 8) * AS_STRIDE + kq]);
                af[mf][2] = __float_as_uint(As[m * AS_STRIDE + kq + 4]);
                af[mf][3] = __float_as_uint(As[(m + 8) * AS_STRIDE + kq + 4]);
            }
#pragma unroll
            for (int nf = 0; nf < 4; nf++) {
                int n = wn * 32 + nf * 8 + (lane >> 2);
                bf[nf][0] = __float_as_uint(Bs[kq * BS_STRIDE + n]);
                bf[nf][1] = __float_as_uint(Bs[(kq + 4) * BS_STRIDE + n]);
            }
#pragma unroll
            for (int mf = 0; mf < 4; mf++)
#pragma unroll
                for (int nf = 0; nf < 4; nf++) {
                    asm volatile(
                        "mma.sync.aligned.m16n8k8.row.col.f32.tf32.tf32.f32 "
                        "{%0,%1,%2,%3}, {%4,%5,%6,%7}, {%8,%9}, {%0,%1,%2,%3};\n"
                        : "+f"(acc[mf][nf][0]), "+f"(acc[mf][nf][1]),
                          "+f"(acc[mf][nf][2]), "+f"(acc[mf][nf][3])
                        : "r"(af[mf][0]), "r"(af[mf][1]),
                          "r"(af[mf][2]), "r"(af[mf][3]),
                          "r"(bf[nf][0]), "r"(bf[nf][1]));
                }
        }
        __syncthreads();
    }

    // Epilogue: bias (+relu), write to g_h (sorted) or scatter to out.
#pragma unroll
    for (int mf = 0; mf < 4; mf++) {
#pragma unroll
        for (int half = 0; half < 2; half++) {
            int r = wm * 64 + mf * 16 + (lane >> 2) + half * 8;
            float* orow = nullptr;
            if (SCATTER) {
                int tok = g_perm[tile * TM + r];
                if (tok >= 0) orow = out + (size_t)tok * N + n0;
            } else {
                orow = out + ((size_t)tile * TM + r) * N + n0;
            }
#pragma unroll
            for (int nf = 0; nf < 4; nf++) {
                int c = wn * 32 + nf * 8 + 2 * (lane & 3);
                float v0 = acc[mf][nf][half * 2 + 0] + bp[c];
                float v1 = acc[mf][nf][half * 2 + 1] + bp[c + 1];
                if (RELU) { v0 = fmaxf(v0, 0.f); v1 = fmaxf(v1, 0.f); }
                if (orow) { orow[c] = v0; orow[c + 1] = v1; }
            }
        }
    }
}

extern "C" void kernel_launch(void* const* d_in, const int* in_sizes, int n_in,
                              void* d_out, int out_size) {
    const float* x      = (const float*)d_in[0];
    const int*   groups = (const int*)d_in[1];   // int32 (or int64 — probed in-kernel)
    const float* W1     = (const float*)d_in[2];
    const float* b1     = (const float*)d_in[3];
    const float* W2     = (const float*)d_in[4];
    const float* b2     = (const float*)d_in[5];
    float*       out    = (float*)d_out;

    route_kernel<<<1, 1024>>>(groups);

    // Layer 1: h = relu(x_gathered @ W1[e] + b1[e])  -> g_h (sorted layout)
    gemm_kernel<D_INc, D_Hc, /*GATHER=*/true, /*RELU=*/true, /*SCATTER=*/false>
        <<<dim3(NT_MAX, D_Hc / BN), 256>>>(x, W1, b1, nullptr);

    // Layer 2: out[tok] = h_sorted @ W2[e] + b2[e]   (scatter to token order)
    gemm_kernel<D_Hc, D_OUTc, /*GATHER=*/false, /*RELU=*/false, /*SCATTER=*/true>
        <<<dim3(NT_MAX, D_OUTc / BN), 256>>>(nullptr, W2, b2, out);
}

// round 4
// speedup vs baseline: 1.0292x; 1.0292x over previous
#include <cuda_runtime.h>
#include <cstdint>
#include <cstddef>

// SubnetGate: hard one-hot MoE MLP.
//   out[t] = relu(x[t] @ W1[e] + b1[e]) @ W2[e] + b2[e],  e = groups[t]
// B=8192, D_IN=512, D_H=2048, D_OUT=512, E=8, fp32; groups int32 (probed).
//
// R4: cp.async double-buffered grouped GEMM (tf32 mma.sync, fp32 accum).
// tf32 rounding applied at fragment load (smem holds raw fp32 bytes).

namespace {
constexpr int B_TOK  = 8192;
constexpr int D_INc  = 512;
constexpr int D_Hc   = 2048;
constexpr int D_OUTc = 512;
constexpr int NE     = 8;
constexpr int TM     = 128;   // M tile
constexpr int NT_MAX = 72;    // max padded M tiles
constexpr int BK     = 32;
constexpr int BN     = 128;
constexpr int AS_STRIDE = 36;   // floats; 144B row, 16B-aligned; banks (4m+k)%32 distinct
constexpr int BS_STRIDE = 136;  // floats; 544B row, 16B-aligned; banks (8k+n)%32 distinct
constexpr int AS_SZ = TM * AS_STRIDE;
constexpr int BS_SZ = BK * BS_STRIDE;
constexpr int SMEM_BYTES = (2 * AS_SZ + 2 * BS_SZ) * 4;  // 71680 B
}

__device__ int   g_perm[NT_MAX * TM];       // padded sorted pos -> token id (-1 = pad)
__device__ int   g_tile_expert[NT_MAX];     // tile -> expert (-1 = inactive)
__device__ float g_h[(size_t)NT_MAX * TM * D_Hc];  // hidden acts, sorted layout

__device__ __forceinline__ float f2tf32(float x) {
    uint32_t r;
    asm("cvt.rna.tf32.f32 %0, %1;" : "=r"(r) : "f"(x));
    return __uint_as_float(r);
}

__device__ __forceinline__ void cp_async16(float* smem_dst, const float* gsrc, bool pred) {
    uint32_t s = (uint32_t)__cvta_generic_to_shared(smem_dst);
    int sz = pred ? 16 : 0;   // src-size 0 => zero-fill
    asm volatile("cp.async.cg.shared.global [%0], [%1], 16, %2;\n"
                 :: "r"(s), "l"(gsrc), "r"(sz));
}

// ---------------------------------------------------------------------------
// Router. Single block. Probes int32 vs int64 layout, then counting-sorts
// tokens into 128-row padded per-expert tiles.
// ---------------------------------------------------------------------------
__global__ void route_kernel(const int* __restrict__ g32) {
    __shared__ int cnt[NE];
    __shared__ int base[NE + 1];
    __shared__ int cur[NE];
    __shared__ int odd_or;
    const int tid = threadIdx.x;

    if (tid < NE) cnt[tid] = 0;
    if (tid == 0) odd_or = 0;
    __syncthreads();

    int acc_or = 0;
    for (int i = 2 * tid + 1; i < B_TOK; i += 2 * blockDim.x) acc_or |= g32[i];
    if (acc_or) atomicOr(&odd_or, 1);
    __syncthreads();
    const bool is_i32 = (odd_or != 0);

    for (int t = tid; t < B_TOK; t += blockDim.x) {
        int e = is_i32 ? g32[t] : g32[2 * t];
        atomicAdd(&cnt[e & (NE - 1)], 1);
    }
    __syncthreads();

    if (tid == 0) {
        int b = 0;
        for (int e = 0; e < NE; e++) {
            base[e] = b;
            cur[e]  = b;
            b += ((cnt[e] + TM - 1) / TM) * TM;
        }
        base[NE] = b;
    }
    __syncthreads();

    for (int i = tid; i < NT_MAX * TM; i += blockDim.x) g_perm[i] = -1;
    for (int t = tid; t < NT_MAX; t += blockDim.x) {
        int row0 = t * TM;
        int e = -1;
        if (row0 < base[NE]) {
            for (int k = 0; k < NE; k++)
                if (row0 >= base[k] && row0 < base[k + 1]) e = k;
        }
        g_tile_expert[t] = e;
    }
    __syncthreads();

    for (int t = tid; t < B_TOK; t += blockDim.x) {
        int e = (is_i32 ? g32[t] : g32[2 * t]) & (NE - 1);
        int pos = atomicAdd(&cur[e], 1);
        g_perm[pos] = t;
    }
}

// ---------------------------------------------------------------------------
// Grouped GEMM, cp.async 2-stage pipeline.
// 128x128 block tile, BK=32, 8 warps (2x4), 64x32 warp tile, tf32 m16n8k8.
// ---------------------------------------------------------------------------
template <int K, int N, bool GATHER, bool RELU, bool SCATTER>
__global__ __launch_bounds__(256, 2)
void gemm_kernel(const float* __restrict__ Ain,
                 const float* __restrict__ W,
                 const float* __restrict__ bias,
                 float* __restrict__ Oin) {
    extern __shared__ float smem[];
    float* AsBase = smem;                 // 2 stages of TM x BK
    float* BsBase = smem + 2 * AS_SZ;     // 2 stages of BK x BN

    const int tile = blockIdx.x;
    const int e = g_tile_expert[tile];
    if (e < 0) return;

    const float* A   = GATHER  ? Ain : g_h;
    float*       out = SCATTER ? Oin : g_h;

    const int n0 = blockIdx.y * BN;
    const float* Wp = W + (size_t)e * K * N + n0;
    const float* bp = bias + (size_t)e * N + n0;

    const int tid  = threadIdx.x;
    const int lane = tid & 31;
    const int warp = tid >> 5;
    const int wm   = warp >> 2;  // 0..1
    const int wn   = warp & 3;   // 0..3

    const int ac4 = (tid & 7) * 4;    // A: col group
    const int bc4 = (tid & 31) * 4;   // B: col group

    // Per-thread A-row pointers (rows (tid>>3)+32j), pad rows -> null.
    const float* arow[4];
#pragma unroll
    for (int j = 0; j < 4; j++) {
        int r = (tid >> 3) + 32 * j;
        if (GATHER) {
            int tok = g_perm[tile * TM + r];
            arow[j] = (tok >= 0) ? (A + (size_t)tok * K) : nullptr;
        } else {
            arow[j] = A + ((size_t)tile * TM + r) * K;
        }
    }

    float acc[4][4][4];
#pragma unroll
    for (int i = 0; i < 4; i++)
#pragma unroll
        for (int j = 0; j < 4; j++)
#pragma unroll
            for (int q = 0; q < 4; q++) acc[i][j][q] = 0.f;

    // Stage loads for k0 into buffer buf.
    auto stage = [&](int k0, int buf) {
        float* as = AsBase + buf * AS_SZ;
        float* bs = BsBase + buf * BS_SZ;
#pragma unroll
        for (int j = 0; j < 4; j++) {
            int r = (tid >> 3) + 32 * j;
            const float* src = arow[j] ? (arow[j] + k0 + ac4) : Ain;
            cp_async16(&as[r * AS_STRIDE + ac4], src, arow[j] != nullptr);
        }
#pragma unroll
        for (int j = 0; j < 4; j++) {
            int kk = (tid >> 5) + 8 * j;
            cp_async16(&bs[kk * BS_STRIDE + bc4], Wp + (size_t)(k0 + kk) * N + bc4, true);
        }
    };

    constexpr int NIT = K / BK;

    stage(0, 0);
    asm volatile("cp.async.commit_group;\n");

    for (int it = 0; it < NIT; it++) {
        const int buf = it & 1;
        if (it + 1 < NIT) {
            stage((it + 1) * BK, buf ^ 1);
            asm volatile("cp.async.commit_group;\n");
            asm volatile("cp.async.wait_group 1;\n");
        } else {
            asm volatile("cp.async.wait_group 0;\n");
        }
        __syncthreads();

        const float* As = AsBase + buf * AS_SZ;
        const float* Bs = BsBase + buf * BS_SZ;

#pragma unroll
        for (int kk = 0; kk < BK; kk += 8) {
            uint32_t af[4][4], bf[4][2];
            const int kq = kk + (lane & 3);
#pragma unroll
            for (int mf = 0; mf < 4; mf++) {
                int m = wm * 64 + mf * 16 + (lane >> 2);
                // m16n8k8.tf32 A frag: a0=(m,k) a1=(m+8,k) a2=(m,k+4) a3=(m+8,k+4)
                af[mf][0] = __float_as_uint(f2tf32(As[m * AS_STRIDE + kq]));
                af[mf][1] = __float_as_uint(f2tf32(As[(m + 8) * AS_STRIDE + kq]));
                af[mf][2] = __float_as_uint(f2tf32(As[m * AS_STRIDE + kq + 4]));
                af[mf][3] = __float_as_uint(f2tf32(As[(m + 8) * AS_STRIDE + kq + 4]));
            }
#pragma unroll
            for (int nf = 0; nf < 4; nf++) {
                int n = wn * 32 + nf * 8 + (lane >> 2);
                bf[nf][0] = __float_as_uint(f2tf32(Bs[kq * BS_STRIDE + n]));
                bf[nf][1] = __float_as_uint(f2tf32(Bs[(kq + 4) * BS_STRIDE + n]));
            }
#pragma unroll
            for (int mf = 0; mf < 4; mf++)
#pragma unroll
                for (int nf = 0; nf < 4; nf++) {
                    asm volatile(
                        "mma.sync.aligned.m16n8k8.row.col.f32.tf32.tf32.f32 "
                        "{%0,%1,%2,%3}, {%4,%5,%6,%7}, {%8,%9}, {%0,%1,%2,%3};\n"
                        : "+f"(acc[mf][nf][0]), "+f"(acc[mf][nf][1]),
                          "+f"(acc[mf][nf][2]), "+f"(acc[mf][nf][3])
                        : "r"(af[mf][0]), "r"(af[mf][1]),
                          "r"(af[mf][2]), "r"(af[mf][3]),
                          "r"(bf[nf][0]), "r"(bf[nf][1]));
                }
        }
        __syncthreads();
    }

    // Epilogue: bias (+relu), write to g_h (sorted) or scatter to out.
#pragma unroll
    for (int mf = 0; mf < 4; mf++) {
#pragma unroll
        for (int half = 0; half < 2; half++) {
            int r = wm * 64 + mf * 16 + (lane >> 2) + half * 8;
            float* orow = nullptr;
            if (SCATTER) {
                int tok = g_perm[tile * TM + r];
                if (tok >= 0) orow = out + (size_t)tok * N + n0;
            } else {
                orow = out + ((size_t)tile * TM + r) * N + n0;
            }
#pragma unroll
            for (int nf = 0; nf < 4; nf++) {
                int c = wn * 32 + nf * 8 + 2 * (lane & 3);
                float v0 = acc[mf][nf][half * 2 + 0] + bp[c];
                float v1 = acc[mf][nf][half * 2 + 1] + bp[c + 1];
                if (RELU) { v0 = fmaxf(v0, 0.f); v1 = fmaxf(v1, 0.f); }
                if (orow) { orow[c] = v0; orow[c + 1] = v1; }
            }
        }
    }
}

extern "C" void kernel_launch(void* const* d_in, const int* in_sizes, int n_in,
                              void* d_out, int out_size) {
    const float* x      = (const float*)d_in[0];
    const int*   groups = (const int*)d_in[1];
    const float* W1     = (const float*)d_in[2];
    const float* b1     = (const float*)d_in[3];
    const float* W2     = (const float*)d_in[4];
    const float* b2     = (const float*)d_in[5];
    float*       out    = (float*)d_out;

    cudaFuncSetAttribute(
        gemm_kernel<D_INc, D_Hc, true, true, false>,
        cudaFuncAttributeMaxDynamicSharedMemorySize, SMEM_BYTES);
    cudaFuncSetAttribute(
        gemm_kernel<D_Hc, D_OUTc, false, false, true>,
        cudaFuncAttributeMaxDynamicSharedMemorySize, SMEM_BYTES);

    route_kernel<<<1, 1024>>>(groups);

    gemm_kernel<D_INc, D_Hc, true, true, false>
        <<<dim3(NT_MAX, D_Hc / BN), 256, SMEM_BYTES>>>(x, W1, b1, nullptr);

    gemm_kernel<D_Hc, D_OUTc, false, false, true>
        <<<dim3(NT_MAX, D_OUTc / BN), 256, SMEM_BYTES>>>(nullptr, W2, b2, out);
}

// round 10
// speedup vs baseline: 1.6264x; 1.5802x over previous
#include <cuda_runtime.h>
#include <cuda_fp16.h>
#include <cstdint>
#include <cstddef>

// SubnetGate hard-routed MoE MLP, sm_103 harness (no tcgen05 under compute_103).
//   out[t] = relu(x[t] @ W1[e] + b1[e]) @ W2[e] + b2[e],  e = groups[t]
// B=8192, D_IN=512, D_H=2048, D_OUT=512, E=8, fp32 I/O (groups int32, probed).
//
// R10: fp16 mma.sync m16n8k16 (fp32 accumulate) — 2x the tf32 mma rate, same
// 11-bit mantissa as tf32. Router reverted to the proven R4 atomic version
// (ballot router had divergent __shfl_sync UB -> launch faults).
// Prep kernels pre-convert: x gathered into sorted half scratch; W transposed
// to K-major half W^T. GEMMs: cp.async double-buffered, h kept half (sorted).

namespace {
constexpr int B_TOK  = 8192;
constexpr int D_IN   = 512;
constexpr int D_H    = 2048;
constexpr int D_OUT  = 512;
constexpr int NE     = 8;
constexpr int TM     = 128;
constexpr int NT_MAX = 72;            // sum ceil(c_e/128) <= 64+7
constexpr int ROWS   = NT_MAX * TM;   // 9216
constexpr int BK     = 64;            // halves per k-tile (128B rows)
constexpr int BN     = 128;
constexpr int ST     = 72;            // smem row stride in halves (conflict-free frag loads)
constexpr int AS_SZ  = TM * ST;       // halves per stage
constexpr int BS_SZ  = BN * ST;
constexpr int SMEM_BYTES = 2 * (AS_SZ + BS_SZ) * 2;   // 73728 B
}

__device__ int g_perm[ROWS];            // sorted pos -> token (-1 = pad)
__device__ int g_tile_expert[NT_MAX];   // tile -> expert (-1 inactive)
__device__ __align__(16) __half g_a1[(size_t)ROWS * D_IN];        // gathered x (half, sorted)
__device__ __align__(16) __half g_w1t[(size_t)NE * D_H * D_IN];   // W1^T [e][n][k] half
__device__ __align__(16) __half g_w2t[(size_t)NE * D_OUT * D_H];  // W2^T [e][n][k] half
__device__ __align__(16) __half g_h[(size_t)ROWS * D_H];          // hidden (half, sorted)

__device__ __forceinline__ uint32_t h2_as_u32(__half2 h) {
    return *reinterpret_cast<uint32_t*>(&h);
}

__device__ __forceinline__ void cp_async16(void* smem_dst, const void* gsrc) {
    uint32_t s = (uint32_t)__cvta_generic_to_shared(smem_dst);
    asm volatile("cp.async.cg.shared.global [%0], [%1], 16;\n" :: "r"(s), "l"(gsrc));
}

// ---------------------------------------------------------------------------
// Router (R4-proven version): single block, shared-counter counting sort into
// 128-row padded per-expert tiles. Probes int32 vs int64 groups layout.
// ---------------------------------------------------------------------------
__global__ void route_kernel(const int* __restrict__ g32) {
    __shared__ int cnt[NE];
    __shared__ int base[NE + 1];
    __shared__ int cur[NE];
    __shared__ int odd_or;
    const int tid = threadIdx.x;

    if (tid < NE) cnt[tid] = 0;
    if (tid == 0) odd_or = 0;
    __syncthreads();

    // dtype probe: int64 data (values 0..7, LE) => all odd int32 words zero
    int acc_or = 0;
    for (int i = 2 * tid + 1; i < B_TOK; i += 2 * blockDim.x) acc_or |= g32[i];
    if (acc_or) atomicOr(&odd_or, 1);
    __syncthreads();
    const bool is_i32 = (odd_or != 0);

    for (int t = tid; t < B_TOK; t += blockDim.x) {
        int e = (is_i32 ? g32[t] : g32[2 * t]) & (NE - 1);
        atomicAdd(&cnt[e], 1);
    }
    __syncthreads();

    if (tid == 0) {
        int b = 0;
        for (int e = 0; e < NE; e++) {
            base[e] = b; cur[e] = b;
            b += ((cnt[e] + TM - 1) / TM) * TM;
        }
        base[NE] = b;
    }
    __syncthreads();

    for (int i = tid; i < ROWS; i += blockDim.x) g_perm[i] = -1;
    for (int t = tid; t < NT_MAX; t += blockDim.x) {
        int row0 = t * TM;
        int e = -1;
        if (row0 < base[NE])
            for (int k = 0; k < NE; k++)
                if (row0 >= base[k] && row0 < base[k + 1]) e = k;
        g_tile_expert[t] = e;
    }
    __syncthreads();

    for (int t = tid; t < B_TOK; t += blockDim.x) {
        int e = (is_i32 ? g32[t] : g32[2 * t]) & (NE - 1);
        int pos = atomicAdd(&cur[e], 1);
        g_perm[pos] = t;
    }
}

// ---------------------------------------------------------------------------
// Prep: gather x rows into sorted padded layout, converted to half.
// Block b covers rows 2b, 2b+1; thread handles 4 floats -> 2 half2 (8B store).
// ---------------------------------------------------------------------------
__global__ void prep_x_kernel(const float* __restrict__ x) {
    const int tid = threadIdx.x;
    const int row = 2 * blockIdx.x + (tid >> 7);
    const int c4  = (tid & 127) * 4;
    const int tok = g_perm[row];
    float4 v = make_float4(0.f, 0.f, 0.f, 0.f);
    if (tok >= 0) v = *(const float4*)(x + (size_t)tok * D_IN + c4);
    uint2 o;
    o.x = h2_as_u32(__floats2half2_rn(v.x, v.y));
    o.y = h2_as_u32(__floats2half2_rn(v.z, v.w));
    *(uint2*)(g_a1 + (size_t)row * D_IN + c4) = o;
}

// ---------------------------------------------------------------------------
// Prep: transpose W [e][K][N] -> W^T [e][N][K], converted to half.
// 32x32 fp32 smem tiles; grid (N/32, K/32, E), 256 threads.
// ---------------------------------------------------------------------------
template <int K, int N, bool W2SEL>
__global__ void prep_w_kernel(const float* __restrict__ src) {
    __shared__ float s[32][33];
    __half* dst = W2SEL ? g_w2t : g_w1t;
    const int tid = threadIdx.x;
    const int bn = blockIdx.x, bk = blockIdx.y, e = blockIdx.z;
    const int r  = tid >> 3;
    const int c4 = (tid & 7) * 4;

    float4 v = *(const float4*)(src + ((size_t)e * K + 32 * bk + r) * N + 32 * bn + c4);
    s[r][c4 + 0] = v.x; s[r][c4 + 1] = v.y; s[r][c4 + 2] = v.z; s[r][c4 + 3] = v.w;
    __syncthreads();

    uint2 o;
    o.x = h2_as_u32(__floats2half2_rn(s[c4 + 0][r], s[c4 + 1][r]));
    o.y = h2_as_u32(__floats2half2_rn(s[c4 + 2][r], s[c4 + 3][r]));
    *(uint2*)(dst + ((size_t)e * N + 32 * bn + r) * K + 32 * bk + c4) = o;
}

// ---------------------------------------------------------------------------
// Grouped GEMM: C = op(A_sorted @ W^T[e] + bias[e])
// 128x128 block tile, BK=64, 8 warps (2x4), 64x32 warp tile, fp16 m16n8k16,
// fp32 accumulate, cp.async double-buffer.
//   LAYER1: A=g_a1, W=g_w1t, relu, -> g_h (half, sorted)
//  !LAYER1: A=g_h,  W=g_w2t,       -> scatter fp32 to out
// ---------------------------------------------------------------------------
template <int K, int NTOT, bool LAYER1>
__global__ __launch_bounds__(256, 2)
void gemm_kernel(const float* __restrict__ bias, float* __restrict__ Oout) {
    extern __shared__ __half smem[];
    __half* AsBase = smem;                    // 2 stages TM x BK (stride ST)
    __half* BsBase = smem + 2 * AS_SZ;        // 2 stages BN x BK (stride ST)

    const int tile = blockIdx.x;
    const int e = g_tile_expert[tile];
    if (e < 0) return;

    const __half* Abase = LAYER1 ? g_a1 : g_h;      // device-side symbol refs
    const __half* Wt    = LAYER1 ? g_w1t : g_w2t;

    const int n0 = blockIdx.y * BN;
    const __half* Arow0 = Abase + (size_t)tile * TM * K;
    const __half* Brow0 = Wt + ((size_t)e * NTOT + n0) * K;
    const float*  bp    = bias + (size_t)e * NTOT + n0;

    const int tid  = threadIdx.x;
    const int lane = tid & 31;
    const int warp = tid >> 5;
    const int wm   = warp >> 2;  // 0..1
    const int wn   = warp & 3;   // 0..3

    float acc[4][4][4];
#pragma unroll
    for (int i = 0; i < 4; i++)
#pragma unroll
        for (int j = 0; j < 4; j++)
#pragma unroll
            for (int q = 0; q < 4; q++) acc[i][j][q] = 0.f;

    // Stage 128 rows x 64 halves for A and B: 1024 16B-chunks each, 256 thr x 4.
    auto stage = [&](int k0, int buf) {
        __half* as = AsBase + buf * AS_SZ;
        __half* bs = BsBase + buf * BS_SZ;
#pragma unroll
        for (int j = 0; j < 4; j++) {
            int c = tid + 256 * j;
            int r = c >> 3;
            int co = (c & 7) * 8;
            cp_async16(&as[r * ST + co], Arow0 + (size_t)r * K + k0 + co);
        }
#pragma unroll
        for (int j = 0; j < 4; j++) {
            int c = tid + 256 * j;
            int r = c >> 3;
            int co = (c & 7) * 8;
            cp_async16(&bs[r * ST + co], Brow0 + (size_t)r * K + k0 + co);
        }
    };

    constexpr int NIT = K / BK;

    stage(0, 0);
    asm volatile("cp.async.commit_group;\n");

    for (int it = 0; it < NIT; it++) {
        const int buf = it & 1;
        if (it + 1 < NIT) {
            stage((it + 1) * BK, buf ^ 1);
            asm volatile("cp.async.commit_group;\n");
            asm volatile("cp.async.wait_group 1;\n");
        } else {
            asm volatile("cp.async.wait_group 0;\n");
        }
        __syncthreads();

        const __half* As = AsBase + buf * AS_SZ;
        const __half* Bs = BsBase + buf * BS_SZ;

#pragma unroll
        for (int ks = 0; ks < BK / 16; ks++) {
            const int kq = ks * 16 + (lane & 3) * 2;
            uint32_t af[4][4], bf[4][2];
#pragma unroll
            for (int mf = 0; mf < 4; mf++) {
                int m = wm * 64 + mf * 16 + (lane >> 2);
                // m16n8k16 f16 A frag: a0=(m,k:k+1) a1=(m+8,k:k+1) a2=(m,k+8:k+9) a3=(m+8,k+8:k+9)
                af[mf][0] = *(const uint32_t*)&As[m * ST + kq];
                af[mf][1] = *(const uint32_t*)&As[(m + 8) * ST + kq];
                af[mf][2] = *(const uint32_t*)&As[m * ST + kq + 8];
                af[mf][3] = *(const uint32_t*)&As[(m + 8) * ST + kq + 8];
            }
#pragma unroll
            for (int nf = 0; nf < 4; nf++) {
                int n = wn * 32 + nf * 8 + (lane >> 2);
                // B frag (col): b0=(k:k+1, n), b1=(k+8:k+9, n); Bs rows n-major, k contiguous
                bf[nf][0] = *(const uint32_t*)&Bs[n * ST + kq];
                bf[nf][1] = *(const uint32_t*)&Bs[n * ST + kq + 8];
            }
#pragma unroll
            for (int mf = 0; mf < 4; mf++)
#pragma unroll
                for (int nf = 0; nf < 4; nf++) {
                    asm volatile(
                        "mma.sync.aligned.m16n8k16.row.col.f32.f16.f16.f32 "
                        "{%0,%1,%2,%3}, {%4,%5,%6,%7}, {%8,%9}, {%0,%1,%2,%3};\n"
                        : "+f"(acc[mf][nf][0]), "+f"(acc[mf][nf][1]),
                          "+f"(acc[mf][nf][2]), "+f"(acc[mf][nf][3])
                        : "r"(af[mf][0]), "r"(af[mf][1]),
                          "r"(af[mf][2]), "r"(af[mf][3]),
                          "r"(bf[nf][0]), "r"(bf[nf][1]));
                }
        }
        __syncthreads();
    }

    // Epilogue: bias (+relu); layer1 -> half g_h (sorted), layer2 -> scatter fp32.
#pragma unroll
    for (int mf = 0; mf < 4; mf++) {
#pragma unroll
        for (int half_i = 0; half_i < 2; half_i++) {
            int r = wm * 64 + mf * 16 + (lane >> 2) + half_i * 8;
            float* orow_f = nullptr;
            __half* orow_h = nullptr;
            if (!LAYER1) {
                int tok = g_perm[tile * TM + r];
                if (tok >= 0) orow_f = Oout + (size_t)tok * NTOT + n0;
            } else {
                orow_h = g_h + ((size_t)tile * TM + r) * NTOT + n0;
            }
#pragma unroll
            for (int nf = 0; nf < 4; nf++) {
                int c = wn * 32 + nf * 8 + 2 * (lane & 3);
                float v0 = acc[mf][nf][half_i * 2 + 0] + bp[c];
                float v1 = acc[mf][nf][half_i * 2 + 1] + bp[c + 1];
                if (LAYER1) { v0 = fmaxf(v0, 0.f); v1 = fmaxf(v1, 0.f); }
                if (!LAYER1) {
                    if (orow_f) { orow_f[c] = v0; orow_f[c + 1] = v1; }
                } else {
                    *(uint32_t*)&orow_h[c] = h2_as_u32(__floats2half2_rn(v0, v1));
                }
            }
        }
    }
}

extern "C" void kernel_launch(void* const* d_in, const int* in_sizes, int n_in,
                              void* d_out, int out_size) {
    const float* x      = (const float*)d_in[0];
    const int*   groups = (const int*)d_in[1];
    const float* W1     = (const float*)d_in[2];
    const float* b1     = (const float*)d_in[3];
    const float* W2     = (const float*)d_in[4];
    const float* b2     = (const float*)d_in[5];
    float*       out    = (float*)d_out;

    cudaFuncSetAttribute(gemm_kernel<D_IN, D_H, true>,
                         cudaFuncAttributeMaxDynamicSharedMemorySize, SMEM_BYTES);
    cudaFuncSetAttribute(gemm_kernel<D_H, D_OUT, false>,
                         cudaFuncAttributeMaxDynamicSharedMemorySize, SMEM_BYTES);

    route_kernel<<<1, 1024>>>(groups);
    prep_x_kernel<<<ROWS / 2, 256>>>(x);
    prep_w_kernel<D_IN, D_H, false><<<dim3(D_H / 32, D_IN / 32, NE), 256>>>(W1);
    prep_w_kernel<D_H, D_OUT, true><<<dim3(D_OUT / 32, D_H / 32, NE), 256>>>(W2);

    // Layer 1: h = relu(x_sorted @ W1^T[e] + b1[e]) -> g_h (half, sorted)
    gemm_kernel<D_IN, D_H, true>
        <<<dim3(NT_MAX, D_H / BN), 256, SMEM_BYTES>>>(b1, nullptr);

    // Layer 2: out[tok] = h @ W2^T[e] + b2[e] (scatter to token order, fp32)
    gemm_kernel<D_H, D_OUT, false>
        <<<dim3(NT_MAX, D_OUT / BN), 256, SMEM_BYTES>>>(b2, out);
}